// round 4
// baseline (speedup 1.0000x reference)
#include <cuda_runtime.h>

// Problem constants (fixed by setup_inputs)
#define BATCH 8
#define P 1024
#define Q 1024
// E  : P x Q            = 1024 x 1024
// Hx : (P-2) x (Q-1)    = 1022 x 1023
// Hy : (P-1) x (Q-2)    = 1023 x 1022

#define HXR (P-2)
#define HXC (Q-1)
#define HYR (P-1)
#define HYC (Q-2)

// KF = 0.5 * [-11/6, 3, -3/2, 1/3]
// KB = -0.5 * reversed = [-1/6, 3/4, -3/2, 11/12]
__device__ __forceinline__ float kf(int d) {
    const float c[4] = {-11.0f/12.0f, 1.5f, -0.75f, 1.0f/6.0f};
    return c[d];
}
__device__ __forceinline__ float kb(int d) {
    const float c[4] = {-1.0f/6.0f, 0.75f, -1.5f, 11.0f/12.0f};
    return c[d];
}

// ---------------------------------------------------------------------------
// amper: E_out[y,x] = E[y,x] + S1(Hy) - S2(Hx)
// ---------------------------------------------------------------------------
__global__ void amper_kernel(const float* __restrict__ E,  long long Eb,
                             const float* __restrict__ Hx, long long Hxb,
                             const float* __restrict__ Hy, long long Hyb,
                             const float* __restrict__ filt,
                             float* __restrict__ Eout, long long Eob)
{
    int x = blockIdx.x * blockDim.x + threadIdx.x;
    int y = blockIdx.y;
    int b = blockIdx.z;
    if (x >= Q) return;

    float f[3][4];
#pragma unroll
    for (int i = 0; i < 3; ++i)
#pragma unroll
        for (int j = 0; j < 4; ++j)
            f[i][j] = __ldg(filt + i * 4 + j);

    const float* e  = E  + (long long)b * Eb;
    const float* hx = Hx + (long long)b * Hxb;
    const float* hy = Hy + (long long)b * Hyb;

    float s = __ldg(e + y * Q + x);

    // ---- S1 (Hy terms), added ----
    // (a) 0.5 * conv(Hy, filt^T) padded (2,2)/(2,2): valid y in [2,1021], x in [2,1021]
    if (y >= 2 && y <= P - 3 && x >= 2 && x <= Q - 3) {
        float a = 0.0f;
#pragma unroll
        for (int di = 0; di < 4; ++di)
#pragma unroll
            for (int dj = 0; dj < 3; ++dj)
                a += __ldg(hy + (y - 2 + di) * HYC + (x - 2 + dj)) * f[dj][di];
        s += 0.5f * a;
    }
    if (x >= 1 && x <= Q - 2) {
        // (b) vertical forward one-sided on Hy col x-1: y in [0, P-5]
        if (y <= P - 5) {
            float t = 0.0f;
#pragma unroll
            for (int d = 0; d < 4; ++d)
                t += __ldg(hy + (y + d) * HYC + (x - 1)) * kf(d);
            s += t;
        }
        // (c) vertical backward: y >= 4
        if (y >= 4) {
            float t = 0.0f;
#pragma unroll
            for (int d = 0; d < 4; ++d)
                t += __ldg(hy + (y - 4 + d) * HYC + (x - 1)) * kb(d);
            s += t;
        }
    }

    // ---- S2 (Hx terms), subtracted ----
    // (a') 0.5 * conv(Hx, filt) padded (2,2)/(2,2)
    if (y >= 2 && y <= P - 3 && x >= 2 && x <= Q - 3) {
        float a = 0.0f;
#pragma unroll
        for (int di = 0; di < 3; ++di)
#pragma unroll
            for (int dj = 0; dj < 4; ++dj)
                a += __ldg(hx + (y - 2 + di) * HXC + (x - 2 + dj)) * f[di][dj];
        s -= 0.5f * a;
    }
    if (y >= 1 && y <= P - 2) {
        // (b') horizontal forward on Hx row y-1: x in [0, Q-5]
        if (x <= Q - 5) {
            float t = 0.0f;
#pragma unroll
            for (int d = 0; d < 4; ++d)
                t += __ldg(hx + (y - 1) * HXC + (x + d)) * kf(d);
            s -= t;
        }
        // (c') horizontal backward: x >= 4
        if (x >= 4) {
            float t = 0.0f;
#pragma unroll
            for (int d = 0; d < 4; ++d)
                t += __ldg(hx + (y - 1) * HXC + (x - 4 + d)) * kb(d);
            s -= t;
        }
    }

    Eout[(long long)b * Eob + y * Q + x] = s;
}

// ---------------------------------------------------------------------------
// faraday: Hx_out[i,j] = Hx[i,j] - S3(E);  Hy_out[i,j] = Hy[i,j] + S4(E)
// ---------------------------------------------------------------------------
__global__ void faraday_kernel(const float* __restrict__ E,  long long Eb,
                               const float* __restrict__ Hx, long long Hxb,
                               const float* __restrict__ Hy, long long Hyb,
                               const float* __restrict__ filt,
                               float* __restrict__ Hxout, long long Hxob,
                               float* __restrict__ Hyout, long long Hyob)
{
    int j = blockIdx.x * blockDim.x + threadIdx.x;
    int i = blockIdx.y;   // gridDim.y = P-1 covers both H-field row ranges
    int b = blockIdx.z;

    float f[3][4];
#pragma unroll
    for (int r = 0; r < 3; ++r)
#pragma unroll
        for (int c = 0; c < 4; ++c)
            f[r][c] = __ldg(filt + r * 4 + c);

    const float* e = E + (long long)b * Eb;

    // ---- Hx update: i in [0, P-3], j in [0, Q-2] ----
    if (i < HXR && j < HXC) {
        float s = __ldg(Hx + (long long)b * Hxb + i * HXC + j);
        // (d) 0.5 * conv(E, filt), W padded (1,1): j in [1, Q-3]
        if (j >= 1 && j <= Q - 3) {
            float a = 0.0f;
#pragma unroll
            for (int di = 0; di < 3; ++di)
#pragma unroll
                for (int dj = 0; dj < 4; ++dj)
                    a += __ldg(e + (i + di) * Q + (j - 1 + dj)) * f[di][dj];
            s -= 0.5f * a;
        }
        // (e) horizontal forward on E row i+1: j in [0, Q-4]
        if (j <= Q - 4) {
            float t = 0.0f;
#pragma unroll
            for (int d = 0; d < 4; ++d)
                t += __ldg(e + (i + 1) * Q + (j + d)) * kf(d);
            s -= t;
        }
        // (f) horizontal backward: j >= 2
        if (j >= 2) {
            float t = 0.0f;
#pragma unroll
            for (int d = 0; d < 4; ++d)
                t += __ldg(e + (i + 1) * Q + (j - 2 + d)) * kb(d);
            s -= t;
        }
        Hxout[(long long)b * Hxob + i * HXC + j] = s;
    }

    // ---- Hy update: i in [0, P-2], j in [0, Q-3] ----
    if (i < HYR && j < HYC) {
        float s = __ldg(Hy + (long long)b * Hyb + i * HYC + j);
        // (g) 0.5 * conv(E, filt^T), H padded (1,1): i in [1, P-3]
        if (i >= 1 && i <= P - 3) {
            float a = 0.0f;
#pragma unroll
            for (int di = 0; di < 4; ++di)
#pragma unroll
                for (int dj = 0; dj < 3; ++dj)
                    a += __ldg(e + (i - 1 + di) * Q + (j + dj)) * f[dj][di];
            s += 0.5f * a;
        }
        // (h) vertical forward on E col j+1: i in [0, P-4]
        if (i <= P - 4) {
            float t = 0.0f;
#pragma unroll
            for (int d = 0; d < 4; ++d)
                t += __ldg(e + (i + d) * Q + (j + 1)) * kf(d);
            s += t;
        }
        // (i) vertical backward: i >= 2
        if (i >= 2) {
            float t = 0.0f;
#pragma unroll
            for (int d = 0; d < 4; ++d)
                t += __ldg(e + (i - 2 + d) * Q + (j + 1)) * kb(d);
            s += t;
        }
        Hyout[(long long)b * Hyob + i * HYC + j] = s;
    }
}

// ---------------------------------------------------------------------------
// Launch: 2 time steps, results written directly into d_out sections.
// d_out layout (flattened tuple, concat along H inside each section):
//   E  : BATCH x (2*P) x Q            @ offset 0
//   Hx : BATCH x (2*HXR) x HXC        @ offset BATCH*2*P*Q
//   Hy : BATCH x (2*HYR) x HYC        @ offset BATCH*2*P*Q + BATCH*2*HXR*HXC
// ---------------------------------------------------------------------------
extern "C" void kernel_launch(void* const* d_in, const int* in_sizes, int n_in,
                              void* d_out, int out_size)
{
    const float* E    = (const float*)d_in[0];
    const float* Hx   = (const float*)d_in[1];
    const float* Hy   = (const float*)d_in[2];
    const float* filt = (const float*)d_in[3];
    float* out = (float*)d_out;

    const long long E_IN_B  = (long long)P * Q;
    const long long HX_IN_B = (long long)HXR * HXC;
    const long long HY_IN_B = (long long)HYR * HYC;

    const long long E_OUT_B  = 2LL * P * Q;
    const long long HX_OUT_B = 2LL * HXR * HXC;
    const long long HY_OUT_B = 2LL * HYR * HYC;

    float* En  = out;
    float* Em  = out + (long long)P * Q;
    float* Hxn = out + (long long)BATCH * E_OUT_B;
    float* Hxm = Hxn + (long long)HXR * HXC;
    float* Hyn = out + (long long)BATCH * E_OUT_B + (long long)BATCH * HX_OUT_B;
    float* Hym = Hyn + (long long)HYR * HYC;

    dim3 blk(128, 1, 1);
    dim3 gA(Q / 128, P, BATCH);                 // (8, 1024, 8)
    dim3 gF((Q + 127) / 128, P - 1, BATCH);     // (8, 1023, 8) covers both H grids

    // Step 1
    amper_kernel<<<gA, blk>>>(E, E_IN_B, Hx, HX_IN_B, Hy, HY_IN_B, filt,
                              En, E_OUT_B);
    faraday_kernel<<<gF, blk>>>(En, E_OUT_B, Hx, HX_IN_B, Hy, HY_IN_B, filt,
                                Hxn, HX_OUT_B, Hyn, HY_OUT_B);
    // Step 2
    amper_kernel<<<gA, blk>>>(En, E_OUT_B, Hxn, HX_OUT_B, Hyn, HY_OUT_B, filt,
                              Em, E_OUT_B);
    faraday_kernel<<<gF, blk>>>(Em, E_OUT_B, Hxn, HX_OUT_B, Hyn, HY_OUT_B, filt,
                                Hxm, HX_OUT_B, Hym, HY_OUT_B);
}

// round 5
// speedup vs baseline: 1.0296x; 1.0296x over previous
#include <cuda_runtime.h>

// Problem constants (fixed by setup_inputs)
#define BATCH 8
#define P 1024
#define Q 1024
#define HXR (P-2)   // 1022
#define HXC (Q-1)   // 1023
#define HYR (P-1)   // 1023
#define HYC (Q-2)   // 1022

#define TX 32
#define TY 16
#define NT (TX*TY)

// KF = 0.5 * [-11/6, 3, -3/2, 1/3] ; KB = -0.5 * reversed(KF_raw)
#define KF0 (-11.0f/12.0f)
#define KF1 ( 1.5f)
#define KF2 (-0.75f)
#define KF3 ( 1.0f/6.0f)
#define KB0 (-1.0f/6.0f)
#define KB1 ( 0.75f)
#define KB2 (-1.5f)
#define KB3 ( 11.0f/12.0f)

// ---------------------------------------------------------------------------
// amper: E_out[y,x] = E[y,x] + S1(Hy) - S2(Hx)
// smem tiles: Hy rows [y0-4, y0+TY+2], cols [x0-2, x0+TX-1]
//             Hx rows [y0-2, y0+TY-1], cols [x0-4, x0+TX+2]
// ---------------------------------------------------------------------------
__global__ __launch_bounds__(NT) void amper_tiled(
    const float* __restrict__ E,  int Eb,
    const float* __restrict__ Hx, int Hxb,
    const float* __restrict__ Hy, int Hyb,
    const float* __restrict__ filt,
    float* __restrict__ Eout, int Eob)
{
    __shared__ float sHy[TY+7][TX+2];
    __shared__ float sHx[TY+2][TX+7];

    const int x0 = blockIdx.x * TX;
    const int y0 = blockIdx.y * TY;
    const int b  = blockIdx.z;
    const int tx = threadIdx.x, ty = threadIdx.y;
    const int tid = ty * TX + tx;

    const float* hy = Hy + b * Hyb;
    const float* hx = Hx + b * Hxb;

    // stage Hy tile (zero-fill OOB)
    #pragma unroll 2
    for (int idx = tid; idx < (TY+7)*(TX+2); idx += NT) {
        int tr = idx / (TX+2), tc = idx % (TX+2);
        int gy = y0 - 4 + tr, gx = x0 - 2 + tc;
        float v = 0.0f;
        if ((unsigned)gy < (unsigned)HYR && (unsigned)gx < (unsigned)HYC)
            v = __ldg(hy + gy * HYC + gx);
        sHy[tr][tc] = v;
    }
    // stage Hx tile
    #pragma unroll 2
    for (int idx = tid; idx < (TY+2)*(TX+7); idx += NT) {
        int tr = idx / (TX+7), tc = idx % (TX+7);
        int gy = y0 - 2 + tr, gx = x0 - 4 + tc;
        float v = 0.0f;
        if ((unsigned)gy < (unsigned)HXR && (unsigned)gx < (unsigned)HXC)
            v = __ldg(hx + gy * HXC + gx);
        sHx[tr][tc] = v;
    }

    float f[3][4];
    #pragma unroll
    for (int i = 0; i < 12; ++i) (&f[0][0])[i] = __ldg(filt + i);

    __syncthreads();

    const int y = y0 + ty, x = x0 + tx;
    float s = __ldg(E + b * Eb + y * Q + x);

    const int r  = ty + 4, c  = tx + 2;   // (y,x) in sHy coords
    const int ry = ty + 2, cx = tx + 4;   // (y,x) in sHx coords

    const bool interior = (y0 >= 4) && (y0 + TY <= P - 4) &&
                          (x0 >= 2) && (x0 + TX <= Q - 2);

    if (interior) {
        // combined 8-tap (shared by S1 column x-1 and S2 row y-1)
        const float h0 = KB0;
        const float h1 = KB1;
        const float h2 = 0.5f*f[1][0] + KB2;
        const float h3 = 0.5f*f[1][1] + KB3;
        const float h4 = 0.5f*f[1][2] + KF0;
        const float h5 = 0.5f*f[1][3] + KF1;
        const float h6 = KF2;
        const float h7 = KF3;

        // S1: Hy terms
        float a = h0*sHy[r-4][c-1] + h1*sHy[r-3][c-1] + h2*sHy[r-2][c-1] + h3*sHy[r-1][c-1]
                + h4*sHy[r  ][c-1] + h5*sHy[r+1][c-1] + h6*sHy[r+2][c-1] + h7*sHy[r+3][c-1];
        #pragma unroll
        for (int di = 0; di < 4; ++di)
            a += 0.5f*f[0][di]*sHy[r-2+di][c-2] + 0.5f*f[2][di]*sHy[r-2+di][c];
        s += a;

        // S2: Hx terms
        float bm = h0*sHx[ry-1][cx-4] + h1*sHx[ry-1][cx-3] + h2*sHx[ry-1][cx-2] + h3*sHx[ry-1][cx-1]
                 + h4*sHx[ry-1][cx  ] + h5*sHx[ry-1][cx+1] + h6*sHx[ry-1][cx+2] + h7*sHx[ry-1][cx+3];
        #pragma unroll
        for (int dj = 0; dj < 4; ++dj)
            bm += 0.5f*f[0][dj]*sHx[ry-2][cx-2+dj] + 0.5f*f[2][dj]*sHx[ry][cx-2+dj];
        s -= bm;
    } else {
        const float kf[4] = {KF0, KF1, KF2, KF3};
        const float kb[4] = {KB0, KB1, KB2, KB3};
        // S1
        if (y >= 2 && y <= P-3 && x >= 2 && x <= Q-3) {
            float a = 0.0f;
            #pragma unroll
            for (int di = 0; di < 4; ++di)
                #pragma unroll
                for (int dj = 0; dj < 3; ++dj)
                    a += sHy[r-2+di][c-2+dj] * f[dj][di];
            s += 0.5f * a;
        }
        if (x >= 1 && x <= Q-2) {
            if (y <= P-5) {
                float t = 0.0f;
                #pragma unroll
                for (int d = 0; d < 4; ++d) t += sHy[r+d][c-1] * kf[d];
                s += t;
            }
            if (y >= 4) {
                float t = 0.0f;
                #pragma unroll
                for (int d = 0; d < 4; ++d) t += sHy[r-4+d][c-1] * kb[d];
                s += t;
            }
        }
        // S2
        if (y >= 2 && y <= P-3 && x >= 2 && x <= Q-3) {
            float a = 0.0f;
            #pragma unroll
            for (int di = 0; di < 3; ++di)
                #pragma unroll
                for (int dj = 0; dj < 4; ++dj)
                    a += sHx[ry-2+di][cx-2+dj] * f[di][dj];
            s -= 0.5f * a;
        }
        if (y >= 1 && y <= P-2) {
            if (x <= Q-5) {
                float t = 0.0f;
                #pragma unroll
                for (int d = 0; d < 4; ++d) t += sHx[ry-1][cx+d] * kf[d];
                s -= t;
            }
            if (x >= 4) {
                float t = 0.0f;
                #pragma unroll
                for (int d = 0; d < 4; ++d) t += sHx[ry-1][cx-4+d] * kb[d];
                s -= t;
            }
        }
    }

    Eout[b * Eob + y * Q + x] = s;
}

// ---------------------------------------------------------------------------
// faraday: Hx_out[i,j] = Hx[i,j] - S3(E);  Hy_out[i,j] = Hy[i,j] + S4(E)
// smem tile: E rows [i0-2, i0+TY+2], cols [j0-2, j0+TX+2]
// ---------------------------------------------------------------------------
__global__ __launch_bounds__(NT) void faraday_tiled(
    const float* __restrict__ E,  int Eb,
    const float* __restrict__ Hx, int Hxb,
    const float* __restrict__ Hy, int Hyb,
    const float* __restrict__ filt,
    float* __restrict__ Hxo, int Hxob,
    float* __restrict__ Hyo, int Hyob)
{
    __shared__ float sE[TY+5][TX+5];

    const int j0 = blockIdx.x * TX;
    const int i0 = blockIdx.y * TY;
    const int b  = blockIdx.z;
    const int tx = threadIdx.x, ty = threadIdx.y;
    const int tid = ty * TX + tx;

    const float* e = E + b * Eb;

    #pragma unroll 2
    for (int idx = tid; idx < (TY+5)*(TX+5); idx += NT) {
        int tr = idx / (TX+5), tc = idx % (TX+5);
        int gi = i0 - 2 + tr, gj = j0 - 2 + tc;
        float v = 0.0f;
        if ((unsigned)gi < (unsigned)P && (unsigned)gj < (unsigned)Q)
            v = __ldg(e + gi * Q + gj);
        sE[tr][tc] = v;
    }

    float f[3][4];
    #pragma unroll
    for (int i = 0; i < 12; ++i) (&f[0][0])[i] = __ldg(filt + i);

    __syncthreads();

    const int i = i0 + ty, j = j0 + tx;
    const int r = ty + 2, c = tx + 2;

    const bool interior = (i0 >= 2) && (i0 + TY <= P - 3) &&
                          (j0 >= 2) && (j0 + TX <= Q - 3);

    if (interior) {
        // combined 6-tap (shared by Hx row i+1 and Hy col j+1)
        const float g0 = KB0;
        const float g1 = 0.5f*f[1][0] + KB1;
        const float g2 = 0.5f*f[1][1] + KF0 + KB2;
        const float g3 = 0.5f*f[1][2] + KF1 + KB3;
        const float g4 = 0.5f*f[1][3] + KF2;
        const float g5 = KF3;

        // Hx update
        float sx = g0*sE[r+1][c-2] + g1*sE[r+1][c-1] + g2*sE[r+1][c]
                 + g3*sE[r+1][c+1] + g4*sE[r+1][c+2] + g5*sE[r+1][c+3];
        #pragma unroll
        for (int dj = 0; dj < 4; ++dj)
            sx += 0.5f*f[0][dj]*sE[r][c-1+dj] + 0.5f*f[2][dj]*sE[r+2][c-1+dj];
        Hxo[b * Hxob + i * HXC + j] = __ldg(Hx + b * Hxb + i * HXC + j) - sx;

        // Hy update
        float sy = g0*sE[r-2][c+1] + g1*sE[r-1][c+1] + g2*sE[r][c+1]
                 + g3*sE[r+1][c+1] + g4*sE[r+2][c+1] + g5*sE[r+3][c+1];
        #pragma unroll
        for (int di = 0; di < 4; ++di)
            sy += 0.5f*f[0][di]*sE[r-1+di][c] + 0.5f*f[2][di]*sE[r-1+di][c+2];
        Hyo[b * Hyob + i * HYC + j] = __ldg(Hy + b * Hyb + i * HYC + j) + sy;
    } else {
        const float kf[4] = {KF0, KF1, KF2, KF3};
        const float kb[4] = {KB0, KB1, KB2, KB3};

        // Hx update: i in [0, HXR), j in [0, HXC)
        if (i < HXR && j < HXC) {
            float s = __ldg(Hx + b * Hxb + i * HXC + j);
            if (j >= 1 && j <= Q-3) {
                float a = 0.0f;
                #pragma unroll
                for (int di = 0; di < 3; ++di)
                    #pragma unroll
                    for (int dj = 0; dj < 4; ++dj)
                        a += sE[r+di][c-1+dj] * f[di][dj];
                s -= 0.5f * a;
            }
            if (j <= Q-4) {
                float t = 0.0f;
                #pragma unroll
                for (int d = 0; d < 4; ++d) t += sE[r+1][c+d] * kf[d];
                s -= t;
            }
            if (j >= 2) {
                float t = 0.0f;
                #pragma unroll
                for (int d = 0; d < 4; ++d) t += sE[r+1][c-2+d] * kb[d];
                s -= t;
            }
            Hxo[b * Hxob + i * HXC + j] = s;
        }

        // Hy update: i in [0, HYR), j in [0, HYC)
        if (i < HYR && j < HYC) {
            float s = __ldg(Hy + b * Hyb + i * HYC + j);
            if (i >= 1 && i <= P-3) {
                float a = 0.0f;
                #pragma unroll
                for (int di = 0; di < 4; ++di)
                    #pragma unroll
                    for (int dj = 0; dj < 3; ++dj)
                        a += sE[r-1+di][c+dj] * f[dj][di];
                s += 0.5f * a;
            }
            if (i <= P-4) {
                float t = 0.0f;
                #pragma unroll
                for (int d = 0; d < 4; ++d) t += sE[r+d][c+1] * kf[d];
                s += t;
            }
            if (i >= 2) {
                float t = 0.0f;
                #pragma unroll
                for (int d = 0; d < 4; ++d) t += sE[r-2+d][c+1] * kb[d];
                s += t;
            }
            Hyo[b * Hyob + i * HYC + j] = s;
        }
    }
}

// ---------------------------------------------------------------------------
// Launch: 2 time steps, results written directly into d_out sections.
// d_out layout (flattened tuple, concat along H inside each section):
//   E  : BATCH x (2*P) x Q       @ 0
//   Hx : BATCH x (2*HXR) x HXC   @ BATCH*2*P*Q
//   Hy : BATCH x (2*HYR) x HYC   @ BATCH*2*P*Q + BATCH*2*HXR*HXC
// ---------------------------------------------------------------------------
extern "C" void kernel_launch(void* const* d_in, const int* in_sizes, int n_in,
                              void* d_out, int out_size)
{
    const float* E    = (const float*)d_in[0];
    const float* Hx   = (const float*)d_in[1];
    const float* Hy   = (const float*)d_in[2];
    const float* filt = (const float*)d_in[3];
    float* out = (float*)d_out;

    const int E_IN_B  = P * Q;
    const int HX_IN_B = HXR * HXC;
    const int HY_IN_B = HYR * HYC;

    const int E_OUT_B  = 2 * P * Q;
    const int HX_OUT_B = 2 * HXR * HXC;
    const int HY_OUT_B = 2 * HYR * HYC;

    float* En  = out;
    float* Em  = out + P * Q;
    float* Hxn = out + (long long)BATCH * E_OUT_B;
    float* Hxm = Hxn + HXR * HXC;
    float* Hyn = Hxn + (long long)BATCH * HX_OUT_B;
    float* Hym = Hyn + HYR * HYC;

    dim3 blk(TX, TY, 1);
    dim3 gA(Q / TX, P / TY, BATCH);                                  // (32, 64, 8)
    dim3 gF((HXC + TX - 1) / TX, (HYR + TY - 1) / TY, BATCH);        // (32, 64, 8)

    // Step 1
    amper_tiled<<<gA, blk>>>(E, E_IN_B, Hx, HX_IN_B, Hy, HY_IN_B, filt,
                             En, E_OUT_B);
    faraday_tiled<<<gF, blk>>>(En, E_OUT_B, Hx, HX_IN_B, Hy, HY_IN_B, filt,
                               Hxn, HX_OUT_B, Hyn, HY_OUT_B);
    // Step 2
    amper_tiled<<<gA, blk>>>(En, E_OUT_B, Hxn, HX_OUT_B, Hyn, HY_OUT_B, filt,
                             Em, E_OUT_B);
    faraday_tiled<<<gF, blk>>>(Em, E_OUT_B, Hxn, HX_OUT_B, Hyn, HY_OUT_B, filt,
                               Hxm, HX_OUT_B, Hym, HY_OUT_B);
}

// round 6
// speedup vs baseline: 1.0504x; 1.0202x over previous
#include <cuda_runtime.h>

// Problem constants (fixed by setup_inputs)
#define BATCH 8
#define P 1024
#define Q 1024
#define HXR (P-2)   // 1022
#define HXC (Q-1)   // 1023
#define HYR (P-1)   // 1023
#define HYC (Q-2)   // 1022

#define TX 32
#define TY 16
#define NT (TX*TY)

// KF = 0.5 * [-11/6, 3, -3/2, 1/3] ; KB = -0.5 * reversed(KF_raw)
#define KF0 (-11.0f/12.0f)
#define KF1 ( 1.5f)
#define KF2 (-0.75f)
#define KF3 ( 1.0f/6.0f)
#define KB0 (-1.0f/6.0f)
#define KB1 ( 0.75f)
#define KB2 (-1.5f)
#define KB3 ( 11.0f/12.0f)

// ---------------------------------------------------------------------------
// amper: E_out[y,x] = E[y,x] + S1(Hy) - S2(Hx)
// smem tiles: Hy rows [y0-4, y0+TY+2], cols [x0-2, x0+TX-1]
//             Hx rows [y0-2, y0+TY-1], cols [x0-4, x0+TX+2]
// ---------------------------------------------------------------------------
__global__ __launch_bounds__(NT) void amper_tiled(
    const float* __restrict__ E,  int Eb,
    const float* __restrict__ Hx, int Hxb,
    const float* __restrict__ Hy, int Hyb,
    const float* __restrict__ filt,
    float* __restrict__ Eout, int Eob)
{
    __shared__ float sHy[TY+7][TX+2];
    __shared__ float sHx[TY+2][TX+7];

    const int x0 = blockIdx.x * TX;
    const int y0 = blockIdx.y * TY;
    const int b  = blockIdx.z;
    const int tx = threadIdx.x, ty = threadIdx.y;
    const int tid = ty * TX + tx;

    const float* hy = Hy + b * Hyb;
    const float* hx = Hx + b * Hxb;

    // stage Hy tile (zero-fill OOB)
    #pragma unroll 2
    for (int idx = tid; idx < (TY+7)*(TX+2); idx += NT) {
        int tr = idx / (TX+2), tc = idx % (TX+2);
        int gy = y0 - 4 + tr, gx = x0 - 2 + tc;
        float v = 0.0f;
        if ((unsigned)gy < (unsigned)HYR && (unsigned)gx < (unsigned)HYC)
            v = __ldg(hy + gy * HYC + gx);
        sHy[tr][tc] = v;
    }
    // stage Hx tile
    #pragma unroll 2
    for (int idx = tid; idx < (TY+2)*(TX+7); idx += NT) {
        int tr = idx / (TX+7), tc = idx % (TX+7);
        int gy = y0 - 2 + tr, gx = x0 - 4 + tc;
        float v = 0.0f;
        if ((unsigned)gy < (unsigned)HXR && (unsigned)gx < (unsigned)HXC)
            v = __ldg(hx + gy * HXC + gx);
        sHx[tr][tc] = v;
    }

    float f[3][4];
    #pragma unroll
    for (int i = 0; i < 12; ++i) (&f[0][0])[i] = __ldg(filt + i);

    __syncthreads();

    const int y = y0 + ty, x = x0 + tx;
    float s = __ldg(E + b * Eb + y * Q + x);

    const int r  = ty + 4, c  = tx + 2;   // (y,x) in sHy coords
    const int ry = ty + 2, cx = tx + 4;   // (y,x) in sHx coords

    const bool interior = (y0 >= 4) && (y0 + TY <= P - 4) &&
                          (x0 >= 2) && (x0 + TX <= Q - 2);

    if (interior) {
        // combined 8-tap (shared by S1 column x-1 and S2 row y-1)
        const float h0 = KB0;
        const float h1 = KB1;
        const float h2 = 0.5f*f[1][0] + KB2;
        const float h3 = 0.5f*f[1][1] + KB3;
        const float h4 = 0.5f*f[1][2] + KF0;
        const float h5 = 0.5f*f[1][3] + KF1;
        const float h6 = KF2;
        const float h7 = KF3;

        // S1: Hy terms
        float a = h0*sHy[r-4][c-1] + h1*sHy[r-3][c-1] + h2*sHy[r-2][c-1] + h3*sHy[r-1][c-1]
                + h4*sHy[r  ][c-1] + h5*sHy[r+1][c-1] + h6*sHy[r+2][c-1] + h7*sHy[r+3][c-1];
        #pragma unroll
        for (int di = 0; di < 4; ++di)
            a += 0.5f*f[0][di]*sHy[r-2+di][c-2] + 0.5f*f[2][di]*sHy[r-2+di][c];
        s += a;

        // S2: Hx terms
        float bm = h0*sHx[ry-1][cx-4] + h1*sHx[ry-1][cx-3] + h2*sHx[ry-1][cx-2] + h3*sHx[ry-1][cx-1]
                 + h4*sHx[ry-1][cx  ] + h5*sHx[ry-1][cx+1] + h6*sHx[ry-1][cx+2] + h7*sHx[ry-1][cx+3];
        #pragma unroll
        for (int dj = 0; dj < 4; ++dj)
            bm += 0.5f*f[0][dj]*sHx[ry-2][cx-2+dj] + 0.5f*f[2][dj]*sHx[ry][cx-2+dj];
        s -= bm;
    } else {
        const float kf[4] = {KF0, KF1, KF2, KF3};
        const float kb[4] = {KB0, KB1, KB2, KB3};
        // S1
        if (y >= 2 && y <= P-3 && x >= 2 && x <= Q-3) {
            float a = 0.0f;
            #pragma unroll
            for (int di = 0; di < 4; ++di)
                #pragma unroll
                for (int dj = 0; dj < 3; ++dj)
                    a += sHy[r-2+di][c-2+dj] * f[dj][di];
            s += 0.5f * a;
        }
        if (x >= 1 && x <= Q-2) {
            if (y <= P-5) {
                float t = 0.0f;
                #pragma unroll
                for (int d = 0; d < 4; ++d) t += sHy[r+d][c-1] * kf[d];
                s += t;
            }
            if (y >= 4) {
                float t = 0.0f;
                #pragma unroll
                for (int d = 0; d < 4; ++d) t += sHy[r-4+d][c-1] * kb[d];
                s += t;
            }
        }
        // S2
        if (y >= 2 && y <= P-3 && x >= 2 && x <= Q-3) {
            float a = 0.0f;
            #pragma unroll
            for (int di = 0; di < 3; ++di)
                #pragma unroll
                for (int dj = 0; dj < 4; ++dj)
                    a += sHx[ry-2+di][cx-2+dj] * f[di][dj];
            s -= 0.5f * a;
        }
        if (y >= 1 && y <= P-2) {
            if (x <= Q-5) {
                float t = 0.0f;
                #pragma unroll
                for (int d = 0; d < 4; ++d) t += sHx[ry-1][cx+d] * kf[d];
                s -= t;
            }
            if (x >= 4) {
                float t = 0.0f;
                #pragma unroll
                for (int d = 0; d < 4; ++d) t += sHx[ry-1][cx-4+d] * kb[d];
                s -= t;
            }
        }
    }

    Eout[b * Eob + y * Q + x] = s;
}

// ---------------------------------------------------------------------------
// faraday: Hx_out[i,j] = Hx[i,j] - S3(E);  Hy_out[i,j] = Hy[i,j] + S4(E)
// smem tile: E rows [i0-2, i0+TY+2], cols [j0-2, j0+TX+2]
// ---------------------------------------------------------------------------
__global__ __launch_bounds__(NT) void faraday_tiled(
    const float* __restrict__ E,  int Eb,
    const float* __restrict__ Hx, int Hxb,
    const float* __restrict__ Hy, int Hyb,
    const float* __restrict__ filt,
    float* __restrict__ Hxo, int Hxob,
    float* __restrict__ Hyo, int Hyob)
{
    __shared__ float sE[TY+5][TX+5];

    const int j0 = blockIdx.x * TX;
    const int i0 = blockIdx.y * TY;
    const int b  = blockIdx.z;
    const int tx = threadIdx.x, ty = threadIdx.y;
    const int tid = ty * TX + tx;

    const float* e = E + b * Eb;

    #pragma unroll 2
    for (int idx = tid; idx < (TY+5)*(TX+5); idx += NT) {
        int tr = idx / (TX+5), tc = idx % (TX+5);
        int gi = i0 - 2 + tr, gj = j0 - 2 + tc;
        float v = 0.0f;
        if ((unsigned)gi < (unsigned)P && (unsigned)gj < (unsigned)Q)
            v = __ldg(e + gi * Q + gj);
        sE[tr][tc] = v;
    }

    float f[3][4];
    #pragma unroll
    for (int i = 0; i < 12; ++i) (&f[0][0])[i] = __ldg(filt + i);

    __syncthreads();

    const int i = i0 + ty, j = j0 + tx;
    const int r = ty + 2, c = tx + 2;

    const bool interior = (i0 >= 2) && (i0 + TY <= P - 3) &&
                          (j0 >= 2) && (j0 + TX <= Q - 3);

    if (interior) {
        // combined 6-tap (shared by Hx row i+1 and Hy col j+1)
        const float g0 = KB0;
        const float g1 = 0.5f*f[1][0] + KB1;
        const float g2 = 0.5f*f[1][1] + KF0 + KB2;
        const float g3 = 0.5f*f[1][2] + KF1 + KB3;
        const float g4 = 0.5f*f[1][3] + KF2;
        const float g5 = KF3;

        // Hx update
        float sx = g0*sE[r+1][c-2] + g1*sE[r+1][c-1] + g2*sE[r+1][c]
                 + g3*sE[r+1][c+1] + g4*sE[r+1][c+2] + g5*sE[r+1][c+3];
        #pragma unroll
        for (int dj = 0; dj < 4; ++dj)
            sx += 0.5f*f[0][dj]*sE[r][c-1+dj] + 0.5f*f[2][dj]*sE[r+2][c-1+dj];
        Hxo[b * Hxob + i * HXC + j] = __ldg(Hx + b * Hxb + i * HXC + j) - sx;

        // Hy update
        float sy = g0*sE[r-2][c+1] + g1*sE[r-1][c+1] + g2*sE[r][c+1]
                 + g3*sE[r+1][c+1] + g4*sE[r+2][c+1] + g5*sE[r+3][c+1];
        #pragma unroll
        for (int di = 0; di < 4; ++di)
            sy += 0.5f*f[0][di]*sE[r-1+di][c] + 0.5f*f[2][di]*sE[r-1+di][c+2];
        Hyo[b * Hyob + i * HYC + j] = __ldg(Hy + b * Hyb + i * HYC + j) + sy;
    } else {
        const float kf[4] = {KF0, KF1, KF2, KF3};
        const float kb[4] = {KB0, KB1, KB2, KB3};

        // Hx update: i in [0, HXR), j in [0, HXC)
        if (i < HXR && j < HXC) {
            float s = __ldg(Hx + b * Hxb + i * HXC + j);
            if (j >= 1 && j <= Q-3) {
                float a = 0.0f;
                #pragma unroll
                for (int di = 0; di < 3; ++di)
                    #pragma unroll
                    for (int dj = 0; dj < 4; ++dj)
                        a += sE[r+di][c-1+dj] * f[di][dj];
                s -= 0.5f * a;
            }
            if (j <= Q-4) {
                float t = 0.0f;
                #pragma unroll
                for (int d = 0; d < 4; ++d) t += sE[r+1][c+d] * kf[d];
                s -= t;
            }
            if (j >= 2) {
                float t = 0.0f;
                #pragma unroll
                for (int d = 0; d < 4; ++d) t += sE[r+1][c-2+d] * kb[d];
                s -= t;
            }
            Hxo[b * Hxob + i * HXC + j] = s;
        }

        // Hy update: i in [0, HYR), j in [0, HYC)
        if (i < HYR && j < HYC) {
            float s = __ldg(Hy + b * Hyb + i * HYC + j);
            if (i >= 1 && i <= P-3) {
                float a = 0.0f;
                #pragma unroll
                for (int di = 0; di < 4; ++di)
                    #pragma unroll
                    for (int dj = 0; dj < 3; ++dj)
                        a += sE[r-1+di][c+dj] * f[dj][di];
                s += 0.5f * a;
            }
            if (i <= P-4) {
                float t = 0.0f;
                #pragma unroll
                for (int d = 0; d < 4; ++d) t += sE[r+d][c+1] * kf[d];
                s += t;
            }
            if (i >= 2) {
                float t = 0.0f;
                #pragma unroll
                for (int d = 0; d < 4; ++d) t += sE[r-2+d][c+1] * kb[d];
                s += t;
            }
            Hyo[b * Hyob + i * HYC + j] = s;
        }
    }
}

// ---------------------------------------------------------------------------
// Launch: 2 time steps, results written directly into d_out sections.
// d_out layout (flattened tuple, concat along H inside each section):
//   E  : BATCH x (2*P) x Q       @ 0
//   Hx : BATCH x (2*HXR) x HXC   @ BATCH*2*P*Q
//   Hy : BATCH x (2*HYR) x HYC   @ BATCH*2*P*Q + BATCH*2*HXR*HXC
// ---------------------------------------------------------------------------
extern "C" void kernel_launch(void* const* d_in, const int* in_sizes, int n_in,
                              void* d_out, int out_size)
{
    const float* E    = (const float*)d_in[0];
    const float* Hx   = (const float*)d_in[1];
    const float* Hy   = (const float*)d_in[2];
    const float* filt = (const float*)d_in[3];
    float* out = (float*)d_out;

    const int E_IN_B  = P * Q;
    const int HX_IN_B = HXR * HXC;
    const int HY_IN_B = HYR * HYC;

    const int E_OUT_B  = 2 * P * Q;
    const int HX_OUT_B = 2 * HXR * HXC;
    const int HY_OUT_B = 2 * HYR * HYC;

    float* En  = out;
    float* Em  = out + P * Q;
    float* Hxn = out + (long long)BATCH * E_OUT_B;
    float* Hxm = Hxn + HXR * HXC;
    float* Hyn = Hxn + (long long)BATCH * HX_OUT_B;
    float* Hym = Hyn + HYR * HYC;

    dim3 blk(TX, TY, 1);
    dim3 gA(Q / TX, P / TY, BATCH);                                  // (32, 64, 8)
    dim3 gF((HXC + TX - 1) / TX, (HYR + TY - 1) / TY, BATCH);        // (32, 64, 8)

    // Step 1
    amper_tiled<<<gA, blk>>>(E, E_IN_B, Hx, HX_IN_B, Hy, HY_IN_B, filt,
                             En, E_OUT_B);
    faraday_tiled<<<gF, blk>>>(En, E_OUT_B, Hx, HX_IN_B, Hy, HY_IN_B, filt,
                               Hxn, HX_OUT_B, Hyn, HY_OUT_B);
    // Step 2
    amper_tiled<<<gA, blk>>>(En, E_OUT_B, Hxn, HX_OUT_B, Hyn, HY_OUT_B, filt,
                             Em, E_OUT_B);
    faraday_tiled<<<gF, blk>>>(Em, E_OUT_B, Hxn, HX_OUT_B, Hyn, HY_OUT_B, filt,
                               Hxm, HX_OUT_B, Hym, HY_OUT_B);
}

// round 7
// speedup vs baseline: 1.2599x; 1.1995x over previous
#include <cuda_runtime.h>

// Problem constants (fixed by setup_inputs)
#define BATCH 8
#define P 1024
#define Q 1024
#define HXR (P-2)   // 1022
#define HXC (Q-1)   // 1023
#define HYR (P-1)   // 1023
#define HYC (Q-2)   // 1022

#define TX 32       // tile cols
#define WY 8        // warps per block (blockDim.y)
#define KY 4        // outputs per thread (y)
#define TROWS (WY*KY)   // 32 tile rows
#define NT (TX*WY)      // 256 threads

// KF = 0.5 * [-11/6, 3, -3/2, 1/3] ; KB = -0.5 * reversed
#define KF0 (-11.0f/12.0f)
#define KF1 ( 1.5f)
#define KF2 (-0.75f)
#define KF3 ( 1.0f/6.0f)
#define KB0 (-1.0f/6.0f)
#define KB1 ( 0.75f)
#define KB2 (-1.5f)
#define KB3 ( 11.0f/12.0f)

// ===========================================================================
// amper: E_out[y,x] = E[y,x] + S1(Hy) - S2(Hx)
// ===========================================================================
__global__ __launch_bounds__(NT) void amper_tiled(
    const float* __restrict__ E,  int Eb,
    const float* __restrict__ Hx, int Hxb,
    const float* __restrict__ Hy, int Hyb,
    const float* __restrict__ filt,
    float* __restrict__ Eout, int Eob)
{
    // sHy: rows [y0-4, y0+TROWS+2] (39), cols [x0-2, x0+TX-1] (34)
    // sHx: rows [y0-2, y0+TROWS-1] (34), cols [x0-4, x0+TX+2] (39)
    __shared__ float sHy[TROWS+7][36];
    __shared__ float sHx[TROWS+2][40];

    const int x0 = blockIdx.x * TX;
    const int y0 = blockIdx.y * TROWS;
    const int b  = blockIdx.z;
    const int tx = threadIdx.x, ty = threadIdx.y;

    const float* hy = Hy + b * Hyb;
    const float* hx = Hx + b * Hxb;

    // stage Hy tile (zero-fill OOB), warp-per-row
    for (int row = ty; row < TROWS+7; row += WY) {
        int gy = y0 - 4 + row;
        #pragma unroll
        for (int col = tx; col < 34; col += TX) {
            int gx = x0 - 2 + col;
            float v = 0.0f;
            if ((unsigned)gy < (unsigned)HYR && (unsigned)gx < (unsigned)HYC)
                v = __ldg(hy + gy * HYC + gx);
            sHy[row][col] = v;
        }
    }
    // stage Hx tile
    for (int row = ty; row < TROWS+2; row += WY) {
        int gy = y0 - 2 + row;
        #pragma unroll
        for (int col = tx; col < 39; col += TX) {
            int gx = x0 - 4 + col;
            float v = 0.0f;
            if ((unsigned)gy < (unsigned)HXR && (unsigned)gx < (unsigned)HXC)
                v = __ldg(hx + gy * HXC + gx);
            sHx[row][col] = v;
        }
    }

    float f[3][4];
    #pragma unroll
    for (int i = 0; i < 12; ++i) (&f[0][0])[i] = __ldg(filt + i);

    __syncthreads();

    const int Y = y0 + ty * KY;          // first output row of this thread
    const int x = x0 + tx;
    const int R  = ty * KY + 4;          // smem row of Y in sHy
    const int RY = ty * KY + 2;          // smem row of Y in sHx
    const int c  = tx + 2;               // smem col of x in sHy
    const int cx = tx + 4;               // smem col of x in sHx

    const bool interior = (y0 >= 4) && (y0 + TROWS <= P - 4) &&
                          (x0 >= 2) && (x0 + TX <= Q - 2);

    float acc[KY] = {0.f, 0.f, 0.f, 0.f};

    if (interior) {
        // combined 8-tap
        const float h0 = KB0, h1 = KB1;
        const float h2 = 0.5f*f[1][0] + KB2;
        const float h3 = 0.5f*f[1][1] + KB3;
        const float h4 = 0.5f*f[1][2] + KF0;
        const float h5 = 0.5f*f[1][3] + KF1;
        const float h6 = KF2, h7 = KF3;
        const float hh[8] = {h0,h1,h2,h3,h4,h5,h6,h7};
        float w0[4], w2[4];
        #pragma unroll
        for (int d = 0; d < 4; ++d) { w0[d] = 0.5f*f[0][d]; w2[d] = 0.5f*f[2][d]; }

        // ---- S1 (Hy), column-wise, added ----
        {   // col c-2 : w0 coeffs, rows Y-2..Y+4
            float v[KY+3];
            #pragma unroll
            for (int t = 0; t < KY+3; ++t) v[t] = sHy[R-2+t][c-2];
            #pragma unroll
            for (int m = 0; m < KY; ++m)
                #pragma unroll
                for (int d = 0; d < 4; ++d) acc[m] += w0[d]*v[m+d];
        }
        {   // col c-1 : 8-tap, rows Y-4..Y+6
            float v[KY+7];
            #pragma unroll
            for (int t = 0; t < KY+7; ++t) v[t] = sHy[R-4+t][c-1];
            #pragma unroll
            for (int m = 0; m < KY; ++m)
                #pragma unroll
                for (int t = 0; t < 8; ++t) acc[m] += hh[t]*v[m+t];
        }
        {   // col c : w2 coeffs
            float v[KY+3];
            #pragma unroll
            for (int t = 0; t < KY+3; ++t) v[t] = sHy[R-2+t][c];
            #pragma unroll
            for (int m = 0; m < KY; ++m)
                #pragma unroll
                for (int d = 0; d < 4; ++d) acc[m] += w2[d]*v[m+d];
        }

        // ---- S2 (Hx), row-wise, subtracted ----
        {   // row RY-2 : only w0 for output m=0
            #pragma unroll
            for (int d = 0; d < 4; ++d) acc[0] -= w0[d]*sHx[RY-2][cx-2+d];
        }
        #pragma unroll
        for (int ro = -1; ro <= 2; ++ro) {  // rows RY-1..RY+2, 8 cols each
            float v[8];
            #pragma unroll
            for (int t = 0; t < 8; ++t) v[t] = sHx[RY+ro][cx-4+t];
            const int m8 = ro + 1;          // 8-tap output
            #pragma unroll
            for (int t = 0; t < 8; ++t) acc[m8] -= hh[t]*v[t];
            if (ro <= 1) {                  // w0 output m = ro+2
                #pragma unroll
                for (int d = 0; d < 4; ++d) acc[ro+2] -= w0[d]*v[d+2];
            }
            if (ro >= 0) {                  // w2 output m = ro
                #pragma unroll
                for (int d = 0; d < 4; ++d) acc[ro] -= w2[d]*v[d+2];
            }
        }
        {   // row RY+3 : only w2 for output m=3
            #pragma unroll
            for (int d = 0; d < 4; ++d) acc[3] -= w2[d]*sHx[RY+3][cx-2+d];
        }
    } else {
        const float kf[4] = {KF0, KF1, KF2, KF3};
        const float kb[4] = {KB0, KB1, KB2, KB3};
        #pragma unroll
        for (int m = 0; m < KY; ++m) {
            const int y = Y + m, r = R + m, ry = RY + m;
            float s = 0.0f;
            // S1
            if (y >= 2 && y <= P-3 && x >= 2 && x <= Q-3) {
                float a = 0.0f;
                #pragma unroll
                for (int di = 0; di < 4; ++di)
                    #pragma unroll
                    for (int dj = 0; dj < 3; ++dj)
                        a += sHy[r-2+di][c-2+dj] * f[dj][di];
                s += 0.5f * a;
            }
            if (x >= 1 && x <= Q-2) {
                if (y <= P-5) {
                    float t = 0.0f;
                    #pragma unroll
                    for (int d = 0; d < 4; ++d) t += sHy[r+d][c-1] * kf[d];
                    s += t;
                }
                if (y >= 4) {
                    float t = 0.0f;
                    #pragma unroll
                    for (int d = 0; d < 4; ++d) t += sHy[r-4+d][c-1] * kb[d];
                    s += t;
                }
            }
            // S2
            if (y >= 2 && y <= P-3 && x >= 2 && x <= Q-3) {
                float a = 0.0f;
                #pragma unroll
                for (int di = 0; di < 3; ++di)
                    #pragma unroll
                    for (int dj = 0; dj < 4; ++dj)
                        a += sHx[ry-2+di][cx-2+dj] * f[di][dj];
                s -= 0.5f * a;
            }
            if (y >= 1 && y <= P-2) {
                if (x <= Q-5) {
                    float t = 0.0f;
                    #pragma unroll
                    for (int d = 0; d < 4; ++d) t += sHx[ry-1][cx+d] * kf[d];
                    s -= t;
                }
                if (x >= 4) {
                    float t = 0.0f;
                    #pragma unroll
                    for (int d = 0; d < 4; ++d) t += sHx[ry-1][cx-4+d] * kb[d];
                    s -= t;
                }
            }
            acc[m] = s;
        }
    }

    const float* e = E + b * Eb;
    float* eo = Eout + b * Eob;
    #pragma unroll
    for (int m = 0; m < KY; ++m)
        eo[(Y+m) * Q + x] = __ldg(e + (Y+m) * Q + x) + acc[m];
}

// ===========================================================================
// faraday: Hx_out[i,j] = Hx[i,j] - S3(E);  Hy_out[i,j] = Hy[i,j] + S4(E)
// ===========================================================================
__global__ __launch_bounds__(NT) void faraday_tiled(
    const float* __restrict__ E,  int Eb,
    const float* __restrict__ Hx, int Hxb,
    const float* __restrict__ Hy, int Hyb,
    const float* __restrict__ filt,
    float* __restrict__ Hxo, int Hxob,
    float* __restrict__ Hyo, int Hyob)
{
    // sE: rows [i0-2, i0+TROWS+2] (37), cols [j0-2, j0+TX+2] (37)
    __shared__ float sE[TROWS+5][40];

    const int j0 = blockIdx.x * TX;
    const int i0 = blockIdx.y * TROWS;
    const int b  = blockIdx.z;
    const int tx = threadIdx.x, ty = threadIdx.y;

    const float* e = E + b * Eb;

    for (int row = ty; row < TROWS+5; row += WY) {
        int gi = i0 - 2 + row;
        #pragma unroll
        for (int col = tx; col < TX+5; col += TX) {
            int gj = j0 - 2 + col;
            float v = 0.0f;
            if ((unsigned)gi < (unsigned)P && (unsigned)gj < (unsigned)Q)
                v = __ldg(e + gi * Q + gj);
            sE[row][col] = v;
        }
    }

    float f[3][4];
    #pragma unroll
    for (int i = 0; i < 12; ++i) (&f[0][0])[i] = __ldg(filt + i);

    __syncthreads();

    const int I = i0 + ty * KY;
    const int j = j0 + tx;
    const int R = ty * KY + 2;
    const int c = tx + 2;

    const bool interior = (i0 >= 2) && (i0 + TROWS <= P - 3) &&
                          (j0 >= 2) && (j0 + TX <= Q - 3);

    if (interior) {
        const float g0 = KB0;
        const float g1 = 0.5f*f[1][0] + KB1;
        const float g2 = 0.5f*f[1][1] + KF0 + KB2;
        const float g3 = 0.5f*f[1][2] + KF1 + KB3;
        const float g4 = 0.5f*f[1][3] + KF2;
        const float g5 = KF3;
        const float gg[6] = {g0,g1,g2,g3,g4,g5};
        float w0[4], w2[4];
        #pragma unroll
        for (int d = 0; d < 4; ++d) { w0[d] = 0.5f*f[0][d]; w2[d] = 0.5f*f[2][d]; }

        float aHx[KY] = {0.f,0.f,0.f,0.f};
        float aHy[KY] = {0.f,0.f,0.f,0.f};

        {   // col c-2 : Hx g0 on row R+m+1
            float v[KY+2];
            #pragma unroll
            for (int t = 0; t < KY+2; ++t) v[t] = sE[R+t][c-2];
            #pragma unroll
            for (int m = 0; m < KY; ++m) aHx[m] += gg[0]*v[m+1];
        }
        {   // col c-1 : Hx g1 row R+m+1; w0[0] row R+m; w2[0] row R+m+2
            float v[KY+2];
            #pragma unroll
            for (int t = 0; t < KY+2; ++t) v[t] = sE[R+t][c-1];
            #pragma unroll
            for (int m = 0; m < KY; ++m)
                aHx[m] += gg[1]*v[m+1] + w0[0]*v[m] + w2[0]*v[m+2];
        }
        {   // col c : Hx g2/w0[1]/w2[1]; Hy w0 column (rows R+m-1..R+m+2)
            float v[KY+3];
            #pragma unroll
            for (int t = 0; t < KY+3; ++t) v[t] = sE[R-1+t][c];
            #pragma unroll
            for (int m = 0; m < KY; ++m) {
                aHx[m] += gg[2]*v[m+2] + w0[1]*v[m+1] + w2[1]*v[m+3];
                #pragma unroll
                for (int d = 0; d < 4; ++d) aHy[m] += w0[d]*v[m+d];
            }
        }
        {   // col c+1 : Hx g3/w0[2]/w2[2]; Hy 6-tap (rows R+m-2..R+m+3)
            float v[KY+5];
            #pragma unroll
            for (int t = 0; t < KY+5; ++t) v[t] = sE[R-2+t][c+1];
            #pragma unroll
            for (int m = 0; m < KY; ++m) {
                aHx[m] += gg[3]*v[m+3] + w0[2]*v[m+2] + w2[2]*v[m+4];
                #pragma unroll
                for (int t = 0; t < 6; ++t) aHy[m] += gg[t]*v[m+t];
            }
        }
        {   // col c+2 : Hx g4/w0[3]/w2[3]; Hy w2 column
            float v[KY+3];
            #pragma unroll
            for (int t = 0; t < KY+3; ++t) v[t] = sE[R-1+t][c+2];
            #pragma unroll
            for (int m = 0; m < KY; ++m) {
                aHx[m] += gg[4]*v[m+2] + w0[3]*v[m+1] + w2[3]*v[m+3];
                #pragma unroll
                for (int d = 0; d < 4; ++d) aHy[m] += w2[d]*v[m+d];
            }
        }
        {   // col c+3 : Hx g5
            float v[KY+2];
            #pragma unroll
            for (int t = 0; t < KY+2; ++t) v[t] = sE[R+t][c+3];
            #pragma unroll
            for (int m = 0; m < KY; ++m) aHx[m] += gg[5]*v[m+1];
        }

        const float* hxi = Hx + b * Hxb;
        const float* hyi = Hy + b * Hyb;
        float* hxo = Hxo + b * Hxob;
        float* hyo = Hyo + b * Hyob;
        #pragma unroll
        for (int m = 0; m < KY; ++m) {
            const int i = I + m;
            hxo[i * HXC + j] = __ldg(hxi + i * HXC + j) - aHx[m];
            hyo[i * HYC + j] = __ldg(hyi + i * HYC + j) + aHy[m];
        }
    } else {
        const float kf[4] = {KF0, KF1, KF2, KF3};
        const float kb[4] = {KB0, KB1, KB2, KB3};
        #pragma unroll
        for (int m = 0; m < KY; ++m) {
            const int i = I + m, r = R + m;
            // Hx
            if (i < HXR && j < HXC) {
                float s = __ldg(Hx + b * Hxb + i * HXC + j);
                if (j >= 1 && j <= Q-3) {
                    float a = 0.0f;
                    #pragma unroll
                    for (int di = 0; di < 3; ++di)
                        #pragma unroll
                        for (int dj = 0; dj < 4; ++dj)
                            a += sE[r+di][c-1+dj] * f[di][dj];
                    s -= 0.5f * a;
                }
                if (j <= Q-4) {
                    float t = 0.0f;
                    #pragma unroll
                    for (int d = 0; d < 4; ++d) t += sE[r+1][c+d] * kf[d];
                    s -= t;
                }
                if (j >= 2) {
                    float t = 0.0f;
                    #pragma unroll
                    for (int d = 0; d < 4; ++d) t += sE[r+1][c-2+d] * kb[d];
                    s -= t;
                }
                Hxo[b * Hxob + i * HXC + j] = s;
            }
            // Hy
            if (i < HYR && j < HYC) {
                float s = __ldg(Hy + b * Hyb + i * HYC + j);
                if (i >= 1 && i <= P-3) {
                    float a = 0.0f;
                    #pragma unroll
                    for (int di = 0; di < 4; ++di)
                        #pragma unroll
                        for (int dj = 0; dj < 3; ++dj)
                            a += sE[r-1+di][c+dj] * f[dj][di];
                    s += 0.5f * a;
                }
                if (i <= P-4) {
                    float t = 0.0f;
                    #pragma unroll
                    for (int d = 0; d < 4; ++d) t += sE[r+d][c+1] * kf[d];
                    s += t;
                }
                if (i >= 2) {
                    float t = 0.0f;
                    #pragma unroll
                    for (int d = 0; d < 4; ++d) t += sE[r-2+d][c+1] * kb[d];
                    s += t;
                }
                Hyo[b * Hyob + i * HYC + j] = s;
            }
        }
    }
}

// ---------------------------------------------------------------------------
// Launch: 2 time steps, results written directly into d_out sections.
// ---------------------------------------------------------------------------
extern "C" void kernel_launch(void* const* d_in, const int* in_sizes, int n_in,
                              void* d_out, int out_size)
{
    const float* E    = (const float*)d_in[0];
    const float* Hx   = (const float*)d_in[1];
    const float* Hy   = (const float*)d_in[2];
    const float* filt = (const float*)d_in[3];
    float* out = (float*)d_out;

    const int E_IN_B  = P * Q;
    const int HX_IN_B = HXR * HXC;
    const int HY_IN_B = HYR * HYC;

    const int E_OUT_B  = 2 * P * Q;
    const int HX_OUT_B = 2 * HXR * HXC;
    const int HY_OUT_B = 2 * HYR * HYC;

    float* En  = out;
    float* Em  = out + P * Q;
    float* Hxn = out + (long long)BATCH * E_OUT_B;
    float* Hxm = Hxn + HXR * HXC;
    float* Hyn = Hxn + (long long)BATCH * HX_OUT_B;
    float* Hym = Hyn + HYR * HYC;

    dim3 blk(TX, WY, 1);
    dim3 g(Q / TX, P / TROWS, BATCH);   // (32, 32, 8) covers both field grids

    // Step 1
    amper_tiled<<<g, blk>>>(E, E_IN_B, Hx, HX_IN_B, Hy, HY_IN_B, filt,
                            En, E_OUT_B);
    faraday_tiled<<<g, blk>>>(En, E_OUT_B, Hx, HX_IN_B, Hy, HY_IN_B, filt,
                              Hxn, HX_OUT_B, Hyn, HY_OUT_B);
    // Step 2
    amper_tiled<<<g, blk>>>(En, E_OUT_B, Hxn, HX_OUT_B, Hyn, HY_OUT_B, filt,
                            Em, E_OUT_B);
    faraday_tiled<<<g, blk>>>(Em, E_OUT_B, Hxn, HX_OUT_B, Hyn, HY_OUT_B, filt,
                              Hxm, HX_OUT_B, Hym, HY_OUT_B);
}